// round 13
// baseline (speedup 1.0000x reference)
#include <cuda_runtime.h>
#include <cuda_fp16.h>
#include <math.h>
#include <stdint.h>

// Problem constants
#define PB   512
#define PS   128
#define PIN  64
#define PACT 8
#define PD   256
#define PH   4
#define PTOPK 8
#define PDH  64
#define PBS  (PB*PS)   // 65536

// ---------------- scratch (static __device__, no allocation) ----------------
__device__ float  g_qkv[PBS * 3 * PD];
__device__ float  g_trans[PBS * PD];
__device__ float  g_ssum[PB * PS * PH];
__device__ int    g_idx[PB * PTOPK];
__device__ float  g_gi[8 * PB * 3 * PD];

// activation half planes (hi / lo)
__device__ __half g_x0h[PBS * PIN], g_x0l[PBS * PIN];
__device__ __half g_h1h[PBS * PD],  g_h1l[PBS * PD];
__device__ __half g_xah[PBS * PD],  g_xal[PBS * PD];
__device__ __half g_cxh[PBS * PD],  g_cxl[PBS * PD];

// weight half planes, transposed to [N][K]
__device__ __half g_w1h[PD * PIN],    g_w1l[PD * PIN];     // [256][64]
__device__ __half g_w2h[PD * PD],     g_w2l[PD * PD];      // [256pad][256]
__device__ __half g_wqh[3 * PD * PD], g_wql[3 * PD * PD];  // [768][256]
__device__ __half g_woh[PD * PD],     g_wol[PD * PD];      // [256][256]

// ================= MMA helpers =================
__device__ __forceinline__ void mma16816(float* c, const uint32_t* a, const uint32_t* b)
{
    asm volatile(
        "mma.sync.aligned.m16n8k16.row.col.f32.f16.f16.f32 "
        "{%0,%1,%2,%3}, {%4,%5,%6,%7}, {%8,%9}, {%0,%1,%2,%3};"
        : "+f"(c[0]), "+f"(c[1]), "+f"(c[2]), "+f"(c[3])
        : "r"(a[0]), "r"(a[1]), "r"(a[2]), "r"(a[3]), "r"(b[0]), "r"(b[1]));
}
__device__ __forceinline__ void ldm_x4(uint32_t* r, uint32_t addr)
{
    asm volatile("ldmatrix.sync.aligned.m8n8.x4.shared.b16 {%0,%1,%2,%3}, [%4];"
                 : "=r"(r[0]), "=r"(r[1]), "=r"(r[2]), "=r"(r[3]) : "r"(addr));
}
__device__ __forceinline__ void cp16(uint32_t dst, const void* src)
{
    asm volatile("cp.async.cg.shared.global [%0], [%1], 16;" :: "r"(dst), "l"(src));
}
#define CP_COMMIT() asm volatile("cp.async.commit_group;")
#define CP_WAIT0()  asm volatile("cp.async.wait_group 0;")
#define CP_WAIT1()  asm volatile("cp.async.wait_group 1;")

// ================= pipelined ldmatrix HMMA GEMM =================
// C[M,N] = A[M,K] @ B[K,N] + bias. A as hi/lo half planes [M][K] row-major,
// B as hi/lo half planes [N][K] (pre-transposed). 3-term split => ~fp32.
// CTA 128x128, 8 warps (2m x 4n) warp tile 64x32, KC=32, double buffered.
#define KC    32
#define LDAB  40                  // halfs per smem row (80B, conflict-free)
#define PLANE (128*LDAB)          // 5120 halfs
#define STAGE (4*PLANE)           // 20480 halfs
#define MM2_SMEM (2*STAGE*2)      // 81920 bytes

template<int ACT, int WF32, int WHL>
__global__ void __launch_bounds__(256, 1)
mm2_gemm(const __half* __restrict__ Ah, const __half* __restrict__ Al,
         const __half* __restrict__ Bh, const __half* __restrict__ Bl,
         const float* __restrict__ bias,
         float* __restrict__ Cf, __half* __restrict__ Ch, __half* __restrict__ Cl,
         int Nreal, int K, int ldc)
{
    extern __shared__ __half sh2[];
    uint32_t sbase = (uint32_t)__cvta_generic_to_shared(sh2);
    int tid = threadIdx.x, wid = tid >> 5, lane = tid & 31;
    int bm = blockIdx.y * 128, bn = blockIdx.x * 128;
    int wm = (wid >> 2) * 64, wn = (wid & 3) * 32;

    const __half* gsrc[4];
    gsrc[0] = Ah + (size_t)bm * K;
    gsrc[1] = Al + (size_t)bm * K;
    gsrc[2] = Bh + (size_t)bn * K;
    gsrc[3] = Bl + (size_t)bn * K;

    int nchunk = K / KC;

    auto issue = [&](int c) {
        int k0 = c * KC;
        uint32_t sb = sbase + (uint32_t)((c & 1) * STAGE) * 2;
#pragma unroll
        for (int p = 0; p < 4; p++) {
#pragma unroll
            for (int i = 0; i < 2; i++) {
                int idx = tid + i * 256;
                int row = idx >> 2, ch = idx & 3;
                const __half* s = gsrc[p] + (size_t)row * K + k0 + ch * 8;
                uint32_t d = sb + (uint32_t)(p * PLANE + row * LDAB + ch * 8) * 2;
                cp16(d, s);
            }
        }
        CP_COMMIT();
    };

    float acc[16][4];
#pragma unroll
    for (int i = 0; i < 16; i++)
#pragma unroll
        for (int j = 0; j < 4; j++) acc[i][j] = 0.f;

    issue(0);
    for (int c = 0; c < nchunk; c++) {
        if (c + 1 < nchunk) { issue(c + 1); CP_WAIT1(); }
        else               { CP_WAIT0(); }
        __syncthreads();

        uint32_t sb  = sbase + (uint32_t)((c & 1) * STAGE) * 2;
        uint32_t sAh = sb;
        uint32_t sAl = sb + (uint32_t)PLANE * 2;
        uint32_t sBh = sb + (uint32_t)(2 * PLANE) * 2;
        uint32_t sBl = sb + (uint32_t)(3 * PLANE) * 2;

#pragma unroll
        for (int ks = 0; ks < 2; ks++) {
            uint32_t afh[4][4], afl[4][4], bfh[4][2], bfl[4][2];
            // A frags: lanes 0-15 rows 0-15 chunk0, lanes 16-31 rows chunk1
            uint32_t aoff = (uint32_t)((wm + (lane & 15)) * LDAB
                                       + ks * 16 + (lane >> 4) * 8) * 2;
#pragma unroll
            for (int mi = 0; mi < 4; mi++) {
                ldm_x4(afh[mi], sAh + aoff + (uint32_t)(mi * 16 * LDAB) * 2);
                ldm_x4(afl[mi], sAl + aoff + (uint32_t)(mi * 16 * LDAB) * 2);
            }
            // B frags: mat = lane>>3; nrow = wn + g*16 + (mat>>1)*8 + (lane&7)
            int mat = lane >> 3;
#pragma unroll
            for (int g = 0; g < 2; g++) {
                uint32_t boff = (uint32_t)((wn + g * 16 + (mat >> 1) * 8 + (lane & 7)) * LDAB
                                           + ks * 16 + (mat & 1) * 8) * 2;
                ldm_x4(&bfh[2 * g][0], sBh + boff);
                ldm_x4(&bfl[2 * g][0], sBl + boff);
            }
#pragma unroll
            for (int mi = 0; mi < 4; mi++)
#pragma unroll
                for (int ni = 0; ni < 4; ni++) {
                    float* cc = acc[mi * 4 + ni];
                    mma16816(cc, afh[mi], bfh[ni]);
                    mma16816(cc, afh[mi], bfl[ni]);
                    mma16816(cc, afl[mi], bfh[ni]);
                }
        }
        __syncthreads();
    }

    // ---- epilogue ----
    int r0 = bm + wm + (lane >> 2);
    int c0 = wn + (lane & 3) * 2;
#pragma unroll
    for (int mi = 0; mi < 4; mi++) {
#pragma unroll
        for (int ni = 0; ni < 4; ni++) {
            float* cc = acc[mi * 4 + ni];
            int colb = bn + c0 + ni * 8;
#pragma unroll
            for (int h = 0; h < 2; h++) {
                int r = r0 + mi * 16 + h * 8;
#pragma unroll
                for (int e = 0; e < 2; e++) {
                    int cl = colb + e;
                    if (cl < Nreal) {
                        float v = cc[h * 2 + e] + bias[cl];
                        if (ACT == 1) v = tanhf(v);
                        if (WF32) Cf[(size_t)r * ldc + cl] = v;
                        if (WHL) {
                            __half hh = __float2half_rn(v);
                            Ch[(size_t)r * ldc + cl] = hh;
                            Cl[(size_t)r * ldc + cl] =
                                __float2half_rn(v - __half2float(hh));
                        }
                    }
                }
            }
        }
    }
}

// ---------------- weight convert+transpose: W[K][Nsrc] -> [Npad][K] hi/lo ---
__global__ void wconv_kernel(const float* __restrict__ W, __half* __restrict__ th,
                             __half* __restrict__ tl, int K, int Nsrc, int Npad)
{
    int idx = blockIdx.x * 256 + threadIdx.x;
    if (idx < Npad * K) {
        int n = idx / K, k = idx % K;
        float f = (n < Nsrc) ? W[(size_t)k * Nsrc + n] : 0.f;
        __half h = __float2half_rn(f);
        th[idx] = h;
        tl[idx] = __float2half_rn(f - __half2float(h));
    }
}

// ---------------- x_obs -> hi/lo planes ----------------
__global__ void xconv_kernel(const float* __restrict__ x)
{
    int idx = blockIdx.x * 256 + threadIdx.x;
    if (idx < PBS * PIN) {
        float f = x[idx];
        __half h = __float2half_rn(f);
        g_x0h[idx] = h;
        g_x0l[idx] = __float2half_rn(f - __half2float(h));
    }
}

// ---------------- a_prev -> xa cols 248..255 (hi/lo) ----------------
__global__ void aprev_kernel(const float* __restrict__ a_prev)
{
    int i = blockIdx.x * 256 + threadIdx.x;
    if (i < PBS * PACT) {
        int r = i >> 3, j = i & 7;
        float f = a_prev[i];
        __half h = __float2half_rn(f);
        size_t o = (size_t)r * PD + (PD - PACT) + j;
        g_xah[o] = h;
        g_xal[o] = __float2half_rn(f - __half2float(h));
    }
}

// ---------------- fused attention per (b,h), fp32; writes ctx hi/lo --------
__global__ void attn_kernel(void)
{
    extern __shared__ float smf[];
    float* qT = smf;
    float* kT = smf + 64 * 132;
    float* sc = smf;                 // overlay
    float* v  = smf + 2 * 64 * 132;

    int bh = blockIdx.x;
    int b = bh >> 2, h = bh & 3;
    int tid = threadIdx.x;
    int tx = tid & 15, ty = tid >> 4;

    const float* base = g_qkv + (size_t)b * PS * (3 * PD) + h * PDH;
    for (int idx = tid; idx < PS * PDH; idx += 256) {
        int s = idx >> 6, d = idx & 63;
        const float* row = base + (size_t)s * (3 * PD) + d;
        qT[d * 132 + s] = row[0];
        kT[d * 132 + s] = row[PD];
        v[s * 64 + d]   = row[2 * PD];
    }
    __syncthreads();

    float acc[8][8];
#pragma unroll
    for (int i = 0; i < 8; i++)
#pragma unroll
        for (int j = 0; j < 8; j++) acc[i][j] = 0.f;

    for (int d = 0; d < PDH; d++) {
        float a[8], bb[8];
        *(float4*)(a)      = *(const float4*)(qT + d * 132 + ty * 8);
        *(float4*)(a + 4)  = *(const float4*)(qT + d * 132 + ty * 8 + 4);
        *(float4*)(bb)     = *(const float4*)(kT + d * 132 + tx * 8);
        *(float4*)(bb + 4) = *(const float4*)(kT + d * 132 + tx * 8 + 4);
#pragma unroll
        for (int i = 0; i < 8; i++)
#pragma unroll
            for (int j = 0; j < 8; j++)
                acc[i][j] += a[i] * bb[j];
    }
    __syncthreads();

#pragma unroll
    for (int i = 0; i < 8; i++)
#pragma unroll
        for (int j = 0; j < 8; j++)
            sc[(ty * 8 + i) * 129 + tx * 8 + j] = acc[i][j] * 0.125f;
    __syncthreads();

    if (tid < PS) {
        float* row = sc + tid * 129;
        float mx = -1e30f, rsum = 0.f;
        for (int c = 0; c < PS; c++) { float x = row[c]; rsum += x; mx = fmaxf(mx, x); }
        g_ssum[((size_t)b * PS + tid) * PH + h] = rsum;
        float esum = 0.f;
        for (int c = 0; c < PS; c++) { float e = expf(row[c] - mx); row[c] = e; esum += e; }
        float inv = 1.f / esum;
        for (int c = 0; c < PS; c++) row[c] *= inv;
    }
    __syncthreads();

    float acc2[8][4];
#pragma unroll
    for (int i = 0; i < 8; i++)
#pragma unroll
        for (int j = 0; j < 4; j++) acc2[i][j] = 0.f;

    for (int k = 0; k < PS; k++) {
        float4 bv = *(const float4*)(v + k * 64 + tx * 4);
#pragma unroll
        for (int i = 0; i < 8; i++) {
            float a = sc[(ty * 8 + i) * 129 + k];
            acc2[i][0] += a * bv.x;
            acc2[i][1] += a * bv.y;
            acc2[i][2] += a * bv.z;
            acc2[i][3] += a * bv.w;
        }
    }
#pragma unroll
    for (int i = 0; i < 8; i++) {
        int q = ty * 8 + i;
        size_t ofs = ((size_t)b * PS + q) * PD + h * PDH + tx * 4;
#pragma unroll
        for (int e = 0; e < 4; e++) {
            float f = acc2[i][e];
            __half hh = __float2half_rn(f);
            g_cxh[ofs + e] = hh;
            g_cxl[ofs + e] = __float2half_rn(f - __half2float(hh));
        }
    }
}

// ---------------- top-k (jax.lax.top_k tie semantics) ----------------
__global__ void topk_kernel(void)
{
    int b = blockIdx.x;
    __shared__ float sums[PS];
    __shared__ unsigned char taken[PS];
    int tid = threadIdx.x;
    const float* p = g_ssum + (size_t)b * PS * PH;
    sums[tid] = p[tid * PH + 0] + p[tid * PH + 1] + p[tid * PH + 2] + p[tid * PH + 3];
    taken[tid] = 0;
    __syncthreads();
    if (tid == 0) {
        for (int t = 0; t < PTOPK; t++) {
            float best = -1e30f; int bi = 0;
            for (int s = 0; s < PS; s++)
                if (!taken[s] && sums[s] > best) { best = sums[s]; bi = s; }
            taken[bi] = 1;
            g_idx[b * PTOPK + t] = bi;
        }
    }
}

// ---------------- gather selected rows ----------------
__global__ void gather_kernel(float* __restrict__ out_reshaped)
{
    int i = blockIdx.x * 256 + threadIdx.x;
    if (i < PB * PTOPK * PD) {
        int b = i >> 11;
        int t = (i >> 8) & 7;
        int c = i & 255;
        int s = g_idx[b * PTOPK + t];
        out_reshaped[i] = g_trans[((size_t)b * PS + s) * PD + c];
    }
}

// ---------------- fp32 SGEMM (GRU split-K only) ----------------
template<int ACT>
__global__ void sgemm_k(const float* __restrict__ A, const float* __restrict__ Bm,
                        const float* __restrict__ bias, float* __restrict__ C,
                        int M, int N, int K, int ldc, int kchunk)
{
    __shared__ float As[8][128];
    __shared__ float Bs[8][128];
    int bm = blockIdx.y * 128, bn = blockIdx.x * 128;
    int tid = threadIdx.x;
    int tx = tid & 15, ty = tid >> 4;
    float acc[8][8];
#pragma unroll
    for (int i = 0; i < 8; i++)
#pragma unroll
        for (int j = 0; j < 8; j++) acc[i][j] = 0.f;
    int kbeg = blockIdx.z * kchunk;
    int kend = kbeg + kchunk; if (kend > K) kend = K;
    int arow = tid >> 1, acol = (tid & 1) * 4;
    int brow = tid >> 5, bcol = (tid & 31) * 4;
    for (int k0 = kbeg; k0 < kend; k0 += 8) {
        float4 av = *(const float4*)(A + (size_t)(bm + arow) * K + k0 + acol);
        int gb = bn + bcol;
        const float* Brow = Bm + (size_t)(k0 + brow) * N;
        float4 bv;
        if (gb + 3 < N) bv = *(const float4*)(Brow + gb);
        else {
            bv.x = (gb + 0 < N) ? Brow[gb + 0] : 0.f;
            bv.y = (gb + 1 < N) ? Brow[gb + 1] : 0.f;
            bv.z = (gb + 2 < N) ? Brow[gb + 2] : 0.f;
            bv.w = (gb + 3 < N) ? Brow[gb + 3] : 0.f;
        }
        __syncthreads();
        As[acol + 0][arow] = av.x; As[acol + 1][arow] = av.y;
        As[acol + 2][arow] = av.z; As[acol + 3][arow] = av.w;
        *(float4*)(&Bs[brow][bcol]) = bv;
        __syncthreads();
#pragma unroll
        for (int kk = 0; kk < 8; kk++) {
            float a[8], b[8];
            *(float4*)(a)     = *(const float4*)(&As[kk][ty * 8]);
            *(float4*)(a + 4) = *(const float4*)(&As[kk][ty * 8 + 4]);
            *(float4*)(b)     = *(const float4*)(&Bs[kk][tx * 8]);
            *(float4*)(b + 4) = *(const float4*)(&Bs[kk][tx * 8 + 4]);
#pragma unroll
            for (int i = 0; i < 8; i++)
#pragma unroll
                for (int j = 0; j < 8; j++)
                    acc[i][j] += a[i] * b[j];
        }
    }
    float* Cz = C + (size_t)blockIdx.z * M * ldc;
#pragma unroll
    for (int i = 0; i < 8; i++) {
        int r = bm + ty * 8 + i;
#pragma unroll
        for (int j = 0; j < 8; j++) {
            int c = bn + tx * 8 + j;
            if (c < N) {
                float v = acc[i][j];
                if (bias != nullptr && blockIdx.z == 0) v += bias[c];
                if (ACT == 1) v = tanhf(v);
                Cz[(size_t)r * ldc + c] = v;
            }
        }
    }
}

// ---------------- GRU gates ----------------
__global__ void gate_kernel(const float* __restrict__ prev_d,
                            const float* __restrict__ W_hh,
                            const float* __restrict__ b_hh,
                            float* __restrict__ new_d)
{
    int b = blockIdx.x;
    int j = threadIdx.x;
    __shared__ float pd[PD];
    pd[j] = prev_d[(size_t)b * PD + j];
    __syncthreads();

    float gir = 0.f, giz = 0.f, gin = 0.f;
#pragma unroll
    for (int z = 0; z < 8; z++) {
        const float* g = g_gi + ((size_t)z * PB + b) * (3 * PD);
        gir += g[j];
        giz += g[PD + j];
        gin += g[2 * PD + j];
    }
    float hr = b_hh[j], hz = b_hh[PD + j], hn = b_hh[2 * PD + j];
    for (int k = 0; k < PD; k++) {
        float p = pd[k];
        const float* wr = W_hh + (size_t)k * (3 * PD);
        hr += p * wr[j];
        hz += p * wr[PD + j];
        hn += p * wr[2 * PD + j];
    }
    float r  = 1.f / (1.f + expf(-(gir + hr)));
    float zg = 1.f / (1.f + expf(-(giz + hz)));
    float n  = tanhf(gin + r * hn);
    new_d[(size_t)b * PD + j] = (1.f - zg) * n + zg * pd[j];
}

// ---------------- launch ----------------
extern "C" void kernel_launch(void* const* d_in, const int* in_sizes, int n_in,
                              void* d_out, int out_size)
{
    const float* prev_d = (const float*)d_in[0];
    const float* x_obs  = (const float*)d_in[1];
    const float* a_prev = (const float*)d_in[2];
    const float* W1     = (const float*)d_in[3];
    const float* b1     = (const float*)d_in[4];
    const float* W2     = (const float*)d_in[5];
    const float* b2     = (const float*)d_in[6];
    const float* Wqkv   = (const float*)d_in[7];
    const float* bqkv   = (const float*)d_in[8];
    const float* Wo     = (const float*)d_in[9];
    const float* bo     = (const float*)d_in[10];
    const float* W_ih   = (const float*)d_in[11];
    const float* b_ih   = (const float*)d_in[12];
    const float* W_hh   = (const float*)d_in[13];
    const float* b_hh   = (const float*)d_in[14];

    float* out = (float*)d_out;
    float* out_new_d    = out;
    float* out_reshaped = out + PB * PD;

    float *p_qkv, *p_trans, *p_gi;
    cudaGetSymbolAddress((void**)&p_qkv,   g_qkv);
    cudaGetSymbolAddress((void**)&p_trans, g_trans);
    cudaGetSymbolAddress((void**)&p_gi,    g_gi);

    __half *x0h, *x0l, *h1h, *h1l, *xah, *xal, *cxh, *cxl;
    __half *w1h, *w1l, *w2h, *w2l, *wqh, *wql, *woh, *wol;
    cudaGetSymbolAddress((void**)&x0h, g_x0h); cudaGetSymbolAddress((void**)&x0l, g_x0l);
    cudaGetSymbolAddress((void**)&h1h, g_h1h); cudaGetSymbolAddress((void**)&h1l, g_h1l);
    cudaGetSymbolAddress((void**)&xah, g_xah); cudaGetSymbolAddress((void**)&xal, g_xal);
    cudaGetSymbolAddress((void**)&cxh, g_cxh); cudaGetSymbolAddress((void**)&cxl, g_cxl);
    cudaGetSymbolAddress((void**)&w1h, g_w1h); cudaGetSymbolAddress((void**)&w1l, g_w1l);
    cudaGetSymbolAddress((void**)&w2h, g_w2h); cudaGetSymbolAddress((void**)&w2l, g_w2l);
    cudaGetSymbolAddress((void**)&wqh, g_wqh); cudaGetSymbolAddress((void**)&wql, g_wql);
    cudaGetSymbolAddress((void**)&woh, g_woh); cudaGetSymbolAddress((void**)&wol, g_wol);

    const int ATTN_SMEM = (2 * 64 * 132 + 128 * 64) * 4;
    cudaFuncSetAttribute(attn_kernel, cudaFuncAttributeMaxDynamicSharedMemorySize, ATTN_SMEM);
    cudaFuncSetAttribute(mm2_gemm<1,0,1>, cudaFuncAttributeMaxDynamicSharedMemorySize, MM2_SMEM);
    cudaFuncSetAttribute(mm2_gemm<0,0,1>, cudaFuncAttributeMaxDynamicSharedMemorySize, MM2_SMEM);
    cudaFuncSetAttribute(mm2_gemm<0,1,0>, cudaFuncAttributeMaxDynamicSharedMemorySize, MM2_SMEM);

    // 0) one-time converts (cheap)
    wconv_kernel<<<(PD * PIN + 255) / 256, 256>>>(W1, w1h, w1l, PIN, PD, PD);
    wconv_kernel<<<(PD * PD + 255) / 256, 256>>>(W2, w2h, w2l, PD, PD - PACT, PD);
    wconv_kernel<<<(3 * PD * PD + 255) / 256, 256>>>(Wqkv, wqh, wql, PD, 3 * PD, 3 * PD);
    wconv_kernel<<<(PD * PD + 255) / 256, 256>>>(Wo, woh, wol, PD, PD, PD);
    xconv_kernel<<<(PBS * PIN + 255) / 256, 256>>>(x_obs);

    // 1) h1 = tanh(x_obs @ W1 + b1) -> hi/lo
    mm2_gemm<1,0,1><<<dim3(2, PBS / 128), 256, MM2_SMEM>>>(
        x0h, x0l, w1h, w1l, b1, nullptr, h1h, h1l, PD, PIN, PD);
    // 2) xa[:, :248] = h1 @ W2 + b2 -> hi/lo
    mm2_gemm<0,0,1><<<dim3(2, PBS / 128), 256, MM2_SMEM>>>(
        h1h, h1l, w2h, w2l, b2, nullptr, xah, xal, PD - PACT, PD, PD);
    // 3) xa[:, 248:] = a_prev
    aprev_kernel<<<(PBS * PACT + 255) / 256, 256>>>(a_prev);
    // 4) qkv = xa @ Wqkv + bqkv -> fp32
    mm2_gemm<0,1,0><<<dim3(6, PBS / 128), 256, MM2_SMEM>>>(
        xah, xal, wqh, wql, bqkv, p_qkv, nullptr, nullptr, 3 * PD, PD, 3 * PD);
    // 5) attention (ctx hi/lo + per-head raw score sums)
    attn_kernel<<<PB * PH, 256, ATTN_SMEM>>>();
    // 6) trans_out = ctx @ Wo + bo -> fp32
    mm2_gemm<0,1,0><<<dim3(2, PBS / 128), 256, MM2_SMEM>>>(
        cxh, cxl, woh, wol, bo, p_trans, nullptr, nullptr, PD, PD, PD);
    // 7) top-k
    topk_kernel<<<PB, PS>>>();
    // 8) gather
    gather_kernel<<<(PB * PTOPK * PD + 255) / 256, 256>>>(out_reshaped);
    // 9) gi partials = reshaped @ W_ih (fp32 split-K)
    sgemm_k<0><<<dim3(6, PB / 128, 8), 256>>>(out_reshaped, W_ih, b_ih, p_gi,
                                              PB, 3 * PD, PTOPK * PD, 3 * PD, PD);
    // 10) GRU gates
    gate_kernel<<<PB, PD>>>(prev_d, W_hh, b_hh, out_new_d);
}

// round 14
// speedup vs baseline: 1.0075x; 1.0075x over previous
#include <cuda_runtime.h>
#include <cuda_fp16.h>
#include <math.h>
#include <stdint.h>

// Problem constants
#define PB   512
#define PS   128
#define PIN  64
#define PACT 8
#define PD   256
#define PH   4
#define PTOPK 8
#define PDH  64
#define PBS  (PB*PS)   // 65536

// ---------------- scratch (static __device__, no allocation) ----------------
__device__ float  g_qkv[PBS * 3 * PD];
__device__ float  g_trans[PBS * PD];
__device__ float  g_ssum[PB * PS * PH];
__device__ int    g_idx[PB * PTOPK];
__device__ float  g_gi[8 * PB * 3 * PD];

// activation half planes (hi / lo)
__device__ __half g_x0h[PBS * PIN], g_x0l[PBS * PIN];
__device__ __half g_h1h[PBS * PD],  g_h1l[PBS * PD];
__device__ __half g_xah[PBS * PD],  g_xal[PBS * PD];
__device__ __half g_cxh[PBS * PD],  g_cxl[PBS * PD];

// weight half planes, transposed to [N][K]
__device__ __half g_w1h[PD * PIN],    g_w1l[PD * PIN];     // [256][64]
__device__ __half g_w2h[PD * PD],     g_w2l[PD * PD];      // [256pad][256]
__device__ __half g_wqh[3 * PD * PD], g_wql[3 * PD * PD];  // [768][256]
__device__ __half g_woh[PD * PD],     g_wol[PD * PD];      // [256][256]

// ================= MMA helpers =================
__device__ __forceinline__ void mma16816(float* c, const uint32_t* a, const uint32_t* b)
{
    asm volatile(
        "mma.sync.aligned.m16n8k16.row.col.f32.f16.f16.f32 "
        "{%0,%1,%2,%3}, {%4,%5,%6,%7}, {%8,%9}, {%0,%1,%2,%3};"
        : "+f"(c[0]), "+f"(c[1]), "+f"(c[2]), "+f"(c[3])
        : "r"(a[0]), "r"(a[1]), "r"(a[2]), "r"(a[3]), "r"(b[0]), "r"(b[1]));
}
__device__ __forceinline__ void ldm_x4(uint32_t* r, uint32_t addr)
{
    asm volatile("ldmatrix.sync.aligned.m8n8.x4.shared.b16 {%0,%1,%2,%3}, [%4];"
                 : "=r"(r[0]), "=r"(r[1]), "=r"(r[2]), "=r"(r[3]) : "r"(addr));
}
__device__ __forceinline__ void cp16(uint32_t dst, const void* src)
{
    asm volatile("cp.async.cg.shared.global [%0], [%1], 16;" :: "r"(dst), "l"(src));
}
#define CP_COMMIT() asm volatile("cp.async.commit_group;")
#define CP_WAIT0()  asm volatile("cp.async.wait_group 0;")
#define CP_WAIT1()  asm volatile("cp.async.wait_group 1;")

// ================= pipelined ldmatrix HMMA GEMM =================
// C[M,N] = A[M,K] @ B[K,N] + bias. A as hi/lo half planes [M][K] row-major,
// B as hi/lo half planes [N][K] (pre-transposed). 3-term split => ~fp32.
// CTA 128x128, 8 warps (2m x 4n) warp tile 64x32, KC=32, double buffered.
#define KC    32
#define LDAB  40                  // halfs per smem row (80B, conflict-free)
#define PLANE (128*LDAB)          // 5120 halfs
#define STAGE (4*PLANE)           // 20480 halfs
#define MM2_SMEM (2*STAGE*2)      // 81920 bytes

template<int ACT, int WF32, int WHL>
__global__ void __launch_bounds__(256, 1)
mm2_gemm(const __half* __restrict__ Ah, const __half* __restrict__ Al,
         const __half* __restrict__ Bh, const __half* __restrict__ Bl,
         const float* __restrict__ bias,
         float* __restrict__ Cf, __half* __restrict__ Ch, __half* __restrict__ Cl,
         int Nreal, int K, int ldc)
{
    extern __shared__ __half sh2[];
    uint32_t sbase = (uint32_t)__cvta_generic_to_shared(sh2);
    int tid = threadIdx.x, wid = tid >> 5, lane = tid & 31;
    int bm = blockIdx.y * 128, bn = blockIdx.x * 128;
    int wm = (wid >> 2) * 64, wn = (wid & 3) * 32;

    const __half* gsrc[4];
    gsrc[0] = Ah + (size_t)bm * K;
    gsrc[1] = Al + (size_t)bm * K;
    gsrc[2] = Bh + (size_t)bn * K;
    gsrc[3] = Bl + (size_t)bn * K;

    int nchunk = K / KC;

    auto issue = [&](int c) {
        int k0 = c * KC;
        uint32_t sb = sbase + (uint32_t)((c & 1) * STAGE) * 2;
#pragma unroll
        for (int p = 0; p < 4; p++) {
#pragma unroll
            for (int i = 0; i < 2; i++) {
                int idx = tid + i * 256;
                int row = idx >> 2, ch = idx & 3;
                const __half* s = gsrc[p] + (size_t)row * K + k0 + ch * 8;
                uint32_t d = sb + (uint32_t)(p * PLANE + row * LDAB + ch * 8) * 2;
                cp16(d, s);
            }
        }
        CP_COMMIT();
    };

    float acc[16][4];
#pragma unroll
    for (int i = 0; i < 16; i++)
#pragma unroll
        for (int j = 0; j < 4; j++) acc[i][j] = 0.f;

    issue(0);
    for (int c = 0; c < nchunk; c++) {
        if (c + 1 < nchunk) { issue(c + 1); CP_WAIT1(); }
        else               { CP_WAIT0(); }
        __syncthreads();

        uint32_t sb  = sbase + (uint32_t)((c & 1) * STAGE) * 2;
        uint32_t sAh = sb;
        uint32_t sAl = sb + (uint32_t)PLANE * 2;
        uint32_t sBh = sb + (uint32_t)(2 * PLANE) * 2;
        uint32_t sBl = sb + (uint32_t)(3 * PLANE) * 2;

#pragma unroll
        for (int ks = 0; ks < 2; ks++) {
            uint32_t afh[4][4], afl[4][4], bfh[4][2], bfl[4][2];
            // A frags: lanes 0-15 rows 0-15 chunk0, lanes 16-31 rows chunk1
            uint32_t aoff = (uint32_t)((wm + (lane & 15)) * LDAB
                                       + ks * 16 + (lane >> 4) * 8) * 2;
#pragma unroll
            for (int mi = 0; mi < 4; mi++) {
                ldm_x4(afh[mi], sAh + aoff + (uint32_t)(mi * 16 * LDAB) * 2);
                ldm_x4(afl[mi], sAl + aoff + (uint32_t)(mi * 16 * LDAB) * 2);
            }
            // B frags: mat = lane>>3; nrow = wn + g*16 + (mat>>1)*8 + (lane&7)
            int mat = lane >> 3;
#pragma unroll
            for (int g = 0; g < 2; g++) {
                uint32_t boff = (uint32_t)((wn + g * 16 + (mat >> 1) * 8 + (lane & 7)) * LDAB
                                           + ks * 16 + (mat & 1) * 8) * 2;
                ldm_x4(&bfh[2 * g][0], sBh + boff);
                ldm_x4(&bfl[2 * g][0], sBl + boff);
            }
#pragma unroll
            for (int mi = 0; mi < 4; mi++)
#pragma unroll
                for (int ni = 0; ni < 4; ni++) {
                    float* cc = acc[mi * 4 + ni];
                    mma16816(cc, afh[mi], bfh[ni]);
                    mma16816(cc, afh[mi], bfl[ni]);
                    mma16816(cc, afl[mi], bfh[ni]);
                }
        }
        __syncthreads();
    }

    // ---- epilogue ----
    int r0 = bm + wm + (lane >> 2);
    int c0 = wn + (lane & 3) * 2;
#pragma unroll
    for (int mi = 0; mi < 4; mi++) {
#pragma unroll
        for (int ni = 0; ni < 4; ni++) {
            float* cc = acc[mi * 4 + ni];
            int colb = bn + c0 + ni * 8;
#pragma unroll
            for (int h = 0; h < 2; h++) {
                int r = r0 + mi * 16 + h * 8;
#pragma unroll
                for (int e = 0; e < 2; e++) {
                    int cl = colb + e;
                    if (cl < Nreal) {
                        float v = cc[h * 2 + e] + bias[cl];
                        if (ACT == 1) v = tanhf(v);
                        if (WF32) Cf[(size_t)r * ldc + cl] = v;
                        if (WHL) {
                            __half hh = __float2half_rn(v);
                            Ch[(size_t)r * ldc + cl] = hh;
                            Cl[(size_t)r * ldc + cl] =
                                __float2half_rn(v - __half2float(hh));
                        }
                    }
                }
            }
        }
    }
}

// ---------------- weight convert+transpose: W[K][Nsrc] -> [Npad][K] hi/lo ---
__global__ void wconv_kernel(const float* __restrict__ W, __half* __restrict__ th,
                             __half* __restrict__ tl, int K, int Nsrc, int Npad)
{
    int idx = blockIdx.x * 256 + threadIdx.x;
    if (idx < Npad * K) {
        int n = idx / K, k = idx % K;
        float f = (n < Nsrc) ? W[(size_t)k * Nsrc + n] : 0.f;
        __half h = __float2half_rn(f);
        th[idx] = h;
        tl[idx] = __float2half_rn(f - __half2float(h));
    }
}

// ---------------- x_obs -> hi/lo planes ----------------
__global__ void xconv_kernel(const float* __restrict__ x)
{
    int idx = blockIdx.x * 256 + threadIdx.x;
    if (idx < PBS * PIN) {
        float f = x[idx];
        __half h = __float2half_rn(f);
        g_x0h[idx] = h;
        g_x0l[idx] = __float2half_rn(f - __half2float(h));
    }
}

// ---------------- a_prev -> xa cols 248..255 (hi/lo) ----------------
__global__ void aprev_kernel(const float* __restrict__ a_prev)
{
    int i = blockIdx.x * 256 + threadIdx.x;
    if (i < PBS * PACT) {
        int r = i >> 3, j = i & 7;
        float f = a_prev[i];
        __half h = __float2half_rn(f);
        size_t o = (size_t)r * PD + (PD - PACT) + j;
        g_xah[o] = h;
        g_xal[o] = __float2half_rn(f - __half2float(h));
    }
}

// ---------------- fused attention per (b,h), fp32; writes ctx hi/lo --------
__global__ void attn_kernel(void)
{
    extern __shared__ float smf[];
    float* qT = smf;
    float* kT = smf + 64 * 132;
    float* sc = smf;                 // overlay
    float* v  = smf + 2 * 64 * 132;

    int bh = blockIdx.x;
    int b = bh >> 2, h = bh & 3;
    int tid = threadIdx.x;
    int tx = tid & 15, ty = tid >> 4;

    const float* base = g_qkv + (size_t)b * PS * (3 * PD) + h * PDH;
    for (int idx = tid; idx < PS * PDH; idx += 256) {
        int s = idx >> 6, d = idx & 63;
        const float* row = base + (size_t)s * (3 * PD) + d;
        qT[d * 132 + s] = row[0];
        kT[d * 132 + s] = row[PD];
        v[s * 64 + d]   = row[2 * PD];
    }
    __syncthreads();

    float acc[8][8];
#pragma unroll
    for (int i = 0; i < 8; i++)
#pragma unroll
        for (int j = 0; j < 8; j++) acc[i][j] = 0.f;

    for (int d = 0; d < PDH; d++) {
        float a[8], bb[8];
        *(float4*)(a)      = *(const float4*)(qT + d * 132 + ty * 8);
        *(float4*)(a + 4)  = *(const float4*)(qT + d * 132 + ty * 8 + 4);
        *(float4*)(bb)     = *(const float4*)(kT + d * 132 + tx * 8);
        *(float4*)(bb + 4) = *(const float4*)(kT + d * 132 + tx * 8 + 4);
#pragma unroll
        for (int i = 0; i < 8; i++)
#pragma unroll
            for (int j = 0; j < 8; j++)
                acc[i][j] += a[i] * bb[j];
    }
    __syncthreads();

#pragma unroll
    for (int i = 0; i < 8; i++)
#pragma unroll
        for (int j = 0; j < 8; j++)
            sc[(ty * 8 + i) * 129 + tx * 8 + j] = acc[i][j] * 0.125f;
    __syncthreads();

    if (tid < PS) {
        float* row = sc + tid * 129;
        float mx = -1e30f, rsum = 0.f;
        for (int c = 0; c < PS; c++) { float x = row[c]; rsum += x; mx = fmaxf(mx, x); }
        g_ssum[((size_t)b * PS + tid) * PH + h] = rsum;
        float esum = 0.f;
        for (int c = 0; c < PS; c++) { float e = expf(row[c] - mx); row[c] = e; esum += e; }
        float inv = 1.f / esum;
        for (int c = 0; c < PS; c++) row[c] *= inv;
    }
    __syncthreads();

    float acc2[8][4];
#pragma unroll
    for (int i = 0; i < 8; i++)
#pragma unroll
        for (int j = 0; j < 4; j++) acc2[i][j] = 0.f;

    for (int k = 0; k < PS; k++) {
        float4 bv = *(const float4*)(v + k * 64 + tx * 4);
#pragma unroll
        for (int i = 0; i < 8; i++) {
            float a = sc[(ty * 8 + i) * 129 + k];
            acc2[i][0] += a * bv.x;
            acc2[i][1] += a * bv.y;
            acc2[i][2] += a * bv.z;
            acc2[i][3] += a * bv.w;
        }
    }
#pragma unroll
    for (int i = 0; i < 8; i++) {
        int q = ty * 8 + i;
        size_t ofs = ((size_t)b * PS + q) * PD + h * PDH + tx * 4;
#pragma unroll
        for (int e = 0; e < 4; e++) {
            float f = acc2[i][e];
            __half hh = __float2half_rn(f);
            g_cxh[ofs + e] = hh;
            g_cxl[ofs + e] = __float2half_rn(f - __half2float(hh));
        }
    }
}

// ---------------- top-k (jax.lax.top_k tie semantics) ----------------
__global__ void topk_kernel(void)
{
    int b = blockIdx.x;
    __shared__ float sums[PS];
    __shared__ unsigned char taken[PS];
    int tid = threadIdx.x;
    const float* p = g_ssum + (size_t)b * PS * PH;
    sums[tid] = p[tid * PH + 0] + p[tid * PH + 1] + p[tid * PH + 2] + p[tid * PH + 3];
    taken[tid] = 0;
    __syncthreads();
    if (tid == 0) {
        for (int t = 0; t < PTOPK; t++) {
            float best = -1e30f; int bi = 0;
            for (int s = 0; s < PS; s++)
                if (!taken[s] && sums[s] > best) { best = sums[s]; bi = s; }
            taken[bi] = 1;
            g_idx[b * PTOPK + t] = bi;
        }
    }
}

// ---------------- gather selected rows ----------------
__global__ void gather_kernel(float* __restrict__ out_reshaped)
{
    int i = blockIdx.x * 256 + threadIdx.x;
    if (i < PB * PTOPK * PD) {
        int b = i >> 11;
        int t = (i >> 8) & 7;
        int c = i & 255;
        int s = g_idx[b * PTOPK + t];
        out_reshaped[i] = g_trans[((size_t)b * PS + s) * PD + c];
    }
}

// ---------------- fp32 SGEMM (GRU split-K only) ----------------
template<int ACT>
__global__ void sgemm_k(const float* __restrict__ A, const float* __restrict__ Bm,
                        const float* __restrict__ bias, float* __restrict__ C,
                        int M, int N, int K, int ldc, int kchunk)
{
    __shared__ float As[8][128];
    __shared__ float Bs[8][128];
    int bm = blockIdx.y * 128, bn = blockIdx.x * 128;
    int tid = threadIdx.x;
    int tx = tid & 15, ty = tid >> 4;
    float acc[8][8];
#pragma unroll
    for (int i = 0; i < 8; i++)
#pragma unroll
        for (int j = 0; j < 8; j++) acc[i][j] = 0.f;
    int kbeg = blockIdx.z * kchunk;
    int kend = kbeg + kchunk; if (kend > K) kend = K;
    int arow = tid >> 1, acol = (tid & 1) * 4;
    int brow = tid >> 5, bcol = (tid & 31) * 4;
    for (int k0 = kbeg; k0 < kend; k0 += 8) {
        float4 av = *(const float4*)(A + (size_t)(bm + arow) * K + k0 + acol);
        int gb = bn + bcol;
        const float* Brow = Bm + (size_t)(k0 + brow) * N;
        float4 bv;
        if (gb + 3 < N) bv = *(const float4*)(Brow + gb);
        else {
            bv.x = (gb + 0 < N) ? Brow[gb + 0] : 0.f;
            bv.y = (gb + 1 < N) ? Brow[gb + 1] : 0.f;
            bv.z = (gb + 2 < N) ? Brow[gb + 2] : 0.f;
            bv.w = (gb + 3 < N) ? Brow[gb + 3] : 0.f;
        }
        __syncthreads();
        As[acol + 0][arow] = av.x; As[acol + 1][arow] = av.y;
        As[acol + 2][arow] = av.z; As[acol + 3][arow] = av.w;
        *(float4*)(&Bs[brow][bcol]) = bv;
        __syncthreads();
#pragma unroll
        for (int kk = 0; kk < 8; kk++) {
            float a[8], b[8];
            *(float4*)(a)     = *(const float4*)(&As[kk][ty * 8]);
            *(float4*)(a + 4) = *(const float4*)(&As[kk][ty * 8 + 4]);
            *(float4*)(b)     = *(const float4*)(&Bs[kk][tx * 8]);
            *(float4*)(b + 4) = *(const float4*)(&Bs[kk][tx * 8 + 4]);
#pragma unroll
            for (int i = 0; i < 8; i++)
#pragma unroll
                for (int j = 0; j < 8; j++)
                    acc[i][j] += a[i] * b[j];
        }
    }
    float* Cz = C + (size_t)blockIdx.z * M * ldc;
#pragma unroll
    for (int i = 0; i < 8; i++) {
        int r = bm + ty * 8 + i;
#pragma unroll
        for (int j = 0; j < 8; j++) {
            int c = bn + tx * 8 + j;
            if (c < N) {
                float v = acc[i][j];
                if (bias != nullptr && blockIdx.z == 0) v += bias[c];
                if (ACT == 1) v = tanhf(v);
                Cz[(size_t)r * ldc + c] = v;
            }
        }
    }
}

// ---------------- GRU gates ----------------
__global__ void gate_kernel(const float* __restrict__ prev_d,
                            const float* __restrict__ W_hh,
                            const float* __restrict__ b_hh,
                            float* __restrict__ new_d)
{
    int b = blockIdx.x;
    int j = threadIdx.x;
    __shared__ float pd[PD];
    pd[j] = prev_d[(size_t)b * PD + j];
    __syncthreads();

    float gir = 0.f, giz = 0.f, gin = 0.f;
#pragma unroll
    for (int z = 0; z < 8; z++) {
        const float* g = g_gi + ((size_t)z * PB + b) * (3 * PD);
        gir += g[j];
        giz += g[PD + j];
        gin += g[2 * PD + j];
    }
    float hr = b_hh[j], hz = b_hh[PD + j], hn = b_hh[2 * PD + j];
    for (int k = 0; k < PD; k++) {
        float p = pd[k];
        const float* wr = W_hh + (size_t)k * (3 * PD);
        hr += p * wr[j];
        hz += p * wr[PD + j];
        hn += p * wr[2 * PD + j];
    }
    float r  = 1.f / (1.f + expf(-(gir + hr)));
    float zg = 1.f / (1.f + expf(-(giz + hz)));
    float n  = tanhf(gin + r * hn);
    new_d[(size_t)b * PD + j] = (1.f - zg) * n + zg * pd[j];
}

// ---------------- launch ----------------
extern "C" void kernel_launch(void* const* d_in, const int* in_sizes, int n_in,
                              void* d_out, int out_size)
{
    const float* prev_d = (const float*)d_in[0];
    const float* x_obs  = (const float*)d_in[1];
    const float* a_prev = (const float*)d_in[2];
    const float* W1     = (const float*)d_in[3];
    const float* b1     = (const float*)d_in[4];
    const float* W2     = (const float*)d_in[5];
    const float* b2     = (const float*)d_in[6];
    const float* Wqkv   = (const float*)d_in[7];
    const float* bqkv   = (const float*)d_in[8];
    const float* Wo     = (const float*)d_in[9];
    const float* bo     = (const float*)d_in[10];
    const float* W_ih   = (const float*)d_in[11];
    const float* b_ih   = (const float*)d_in[12];
    const float* W_hh   = (const float*)d_in[13];
    const float* b_hh   = (const float*)d_in[14];

    float* out = (float*)d_out;
    float* out_new_d    = out;
    float* out_reshaped = out + PB * PD;

    float *p_qkv, *p_trans, *p_gi;
    cudaGetSymbolAddress((void**)&p_qkv,   g_qkv);
    cudaGetSymbolAddress((void**)&p_trans, g_trans);
    cudaGetSymbolAddress((void**)&p_gi,    g_gi);

    __half *x0h, *x0l, *h1h, *h1l, *xah, *xal, *cxh, *cxl;
    __half *w1h, *w1l, *w2h, *w2l, *wqh, *wql, *woh, *wol;
    cudaGetSymbolAddress((void**)&x0h, g_x0h); cudaGetSymbolAddress((void**)&x0l, g_x0l);
    cudaGetSymbolAddress((void**)&h1h, g_h1h); cudaGetSymbolAddress((void**)&h1l, g_h1l);
    cudaGetSymbolAddress((void**)&xah, g_xah); cudaGetSymbolAddress((void**)&xal, g_xal);
    cudaGetSymbolAddress((void**)&cxh, g_cxh); cudaGetSymbolAddress((void**)&cxl, g_cxl);
    cudaGetSymbolAddress((void**)&w1h, g_w1h); cudaGetSymbolAddress((void**)&w1l, g_w1l);
    cudaGetSymbolAddress((void**)&w2h, g_w2h); cudaGetSymbolAddress((void**)&w2l, g_w2l);
    cudaGetSymbolAddress((void**)&wqh, g_wqh); cudaGetSymbolAddress((void**)&wql, g_wql);
    cudaGetSymbolAddress((void**)&woh, g_woh); cudaGetSymbolAddress((void**)&wol, g_wol);

    const int ATTN_SMEM = (2 * 64 * 132 + 128 * 64) * 4;
    cudaFuncSetAttribute(attn_kernel, cudaFuncAttributeMaxDynamicSharedMemorySize, ATTN_SMEM);
    cudaFuncSetAttribute(mm2_gemm<1,0,1>, cudaFuncAttributeMaxDynamicSharedMemorySize, MM2_SMEM);
    cudaFuncSetAttribute(mm2_gemm<0,0,1>, cudaFuncAttributeMaxDynamicSharedMemorySize, MM2_SMEM);
    cudaFuncSetAttribute(mm2_gemm<0,1,0>, cudaFuncAttributeMaxDynamicSharedMemorySize, MM2_SMEM);

    // 0) one-time converts (cheap)
    wconv_kernel<<<(PD * PIN + 255) / 256, 256>>>(W1, w1h, w1l, PIN, PD, PD);
    wconv_kernel<<<(PD * PD + 255) / 256, 256>>>(W2, w2h, w2l, PD, PD - PACT, PD);
    wconv_kernel<<<(3 * PD * PD + 255) / 256, 256>>>(Wqkv, wqh, wql, PD, 3 * PD, 3 * PD);
    wconv_kernel<<<(PD * PD + 255) / 256, 256>>>(Wo, woh, wol, PD, PD, PD);
    xconv_kernel<<<(PBS * PIN + 255) / 256, 256>>>(x_obs);

    // 1) h1 = tanh(x_obs @ W1 + b1) -> hi/lo
    mm2_gemm<1,0,1><<<dim3(2, PBS / 128), 256, MM2_SMEM>>>(
        x0h, x0l, w1h, w1l, b1, nullptr, h1h, h1l, PD, PIN, PD);
    // 2) xa[:, :248] = h1 @ W2 + b2 -> hi/lo
    mm2_gemm<0,0,1><<<dim3(2, PBS / 128), 256, MM2_SMEM>>>(
        h1h, h1l, w2h, w2l, b2, nullptr, xah, xal, PD - PACT, PD, PD);
    // 3) xa[:, 248:] = a_prev
    aprev_kernel<<<(PBS * PACT + 255) / 256, 256>>>(a_prev);
    // 4) qkv = xa @ Wqkv + bqkv -> fp32
    mm2_gemm<0,1,0><<<dim3(6, PBS / 128), 256, MM2_SMEM>>>(
        xah, xal, wqh, wql, bqkv, p_qkv, nullptr, nullptr, 3 * PD, PD, 3 * PD);
    // 5) attention (ctx hi/lo + per-head raw score sums)
    attn_kernel<<<PB * PH, 256, ATTN_SMEM>>>();
    // 6) trans_out = ctx @ Wo + bo -> fp32
    mm2_gemm<0,1,0><<<dim3(2, PBS / 128), 256, MM2_SMEM>>>(
        cxh, cxl, woh, wol, bo, p_trans, nullptr, nullptr, PD, PD, PD);
    // 7) top-k
    topk_kernel<<<PB, PS>>>();
    // 8) gather
    gather_kernel<<<(PB * PTOPK * PD + 255) / 256, 256>>>(out_reshaped);
    // 9) gi partials = reshaped @ W_ih (fp32 split-K)
    sgemm_k<0><<<dim3(6, PB / 128, 8), 256>>>(out_reshaped, W_ih, b_ih, p_gi,
                                              PB, 3 * PD, PTOPK * PD, 3 * PD, PD);
    // 10) GRU gates
    gate_kernel<<<PB, PD>>>(prev_d, W_hh, b_hh, out_new_d);
}